// round 15
// baseline (speedup 1.0000x reference)
#include <cuda_runtime.h>
#include <cuda_fp16.h>
#include <cstdint>

constexpr int TPB  = 128;   // 4 warps, each owns M=32 rows of TWO tiles
constexpr int TILE = 128;

// ---- weight SMEM: strides ≡ 16·odd (mod 128) -> ldmatrix conflict-free ----
constexpr int ST16 = 48;     // K=16 regions (32B data)
constexpr int ST64 = 144;    // K=64 regions (128B data)

constexpr int RB_C0 = 0;                        // 64 rows x 48 (geo K=16)
constexpr int RB_S1 = RB_C0 + 64*ST16;          // 3072,  64 x 144
constexpr int RB_S2 = RB_S1 + 64*ST64;          // 12288, 16 x 144
constexpr int RB_C1 = RB_S2 + 16*ST64;          // 14592, 64 x 144
constexpr int RB_C2 = RB_C1 + 64*ST64;          // 23808, 64 x 144
constexpr int RB_C3 = RB_C2 + 64*ST64;          // 33024, 8 x 144
constexpr int WT_BYTES = RB_C3 + 8*ST64;        // 34176

constexpr int SM_WS0F = WT_BYTES;               // fp32 ws0 [3][64] = 768 B
constexpr int SM_WVF  = SM_WS0F + 768;          // fp32 wc0 view rows [3][64] = 768 B
constexpr int SM_OUT  = SM_WVF + 768;           // 4w * 2tiles * 32r * 5 f32
constexpr int SMEM_TOTAL = SM_OUT + 4*2*32*5*4; // 40832 -> 2 CTAs/SM

// ---------------- PTX helpers ----------------
__device__ __forceinline__ uint32_t smem_u32(const void* p) {
    uint32_t a; asm("{ .reg .u64 t; cvta.to.shared.u64 t, %1; cvt.u32.u64 %0, t; }" : "=r"(a) : "l"(p));
    return a;
}
__device__ __forceinline__ void mma16816(float c[4], const uint32_t a[4], uint32_t b0, uint32_t b1) {
    asm volatile("mma.sync.aligned.m16n8k16.row.col.f32.f16.f16.f32 "
        "{%0,%1,%2,%3},{%4,%5,%6,%7},{%8,%9},{%0,%1,%2,%3};"
        : "+f"(c[0]), "+f"(c[1]), "+f"(c[2]), "+f"(c[3])
        : "r"(a[0]), "r"(a[1]), "r"(a[2]), "r"(a[3]), "r"(b0), "r"(b1));
}
__device__ __forceinline__ void mma16816h(uint32_t d[2], const uint32_t a[4], uint32_t b0, uint32_t b1) {
    asm volatile("mma.sync.aligned.m16n8k16.row.col.f16.f16.f16.f16 "
        "{%0,%1},{%2,%3,%4,%5},{%6,%7},{%0,%1};"
        : "+r"(d[0]), "+r"(d[1])
        : "r"(a[0]), "r"(a[1]), "r"(a[2]), "r"(a[3]), "r"(b0), "r"(b1));
}
__device__ __forceinline__ void ldm4(uint32_t r[4], uint32_t addr) {
    asm volatile("ldmatrix.sync.aligned.m8n8.x4.shared.b16 {%0,%1,%2,%3}, [%4];"
        : "=r"(r[0]), "=r"(r[1]), "=r"(r[2]), "=r"(r[3]) : "r"(addr));
}
__device__ __forceinline__ void ldm2(uint32_t r[2], uint32_t addr) {
    asm volatile("ldmatrix.sync.aligned.m8n8.x2.shared.b16 {%0,%1}, [%2];"
        : "=r"(r[0]), "=r"(r[1]) : "r"(addr));
}
__device__ __forceinline__ uint32_t pack2(float f0, float f1) {
    uint32_t h;
    asm("cvt.rn.f16x2.f32 %0, %1, %2;" : "=r"(h) : "f"(f1), "f"(f0));
    return h;
}
__device__ __forceinline__ uint32_t relu2(uint32_t v) {
    uint32_t r;
    asm("max.f16x2 %0, %1, %2;" : "=r"(r) : "r"(v), "r"(0u));
    return r;
}
__device__ __forceinline__ uint32_t shfl_u(uint32_t v, int src) {
    return __shfl_sync(0xffffffffu, v, src);
}
__device__ __forceinline__ float2 h2f(uint32_t h) {
    __half2 hh = *reinterpret_cast<__half2*>(&h);
    return __half22float2(hh);
}

// ---- fused dual-tile hidden layer (fp16 acc): one ldm4 feeds both tiles ----
template<int KT, int STRIDE, int RBASE>
__device__ __forceinline__ void layer_h2(uint32_t abase,
                                         const uint32_t ainA[2][4][4],
                                         const uint32_t ainB[2][4][4],
                                         uint32_t aoutA[2][4][4],
                                         uint32_t aoutB[2][4][4])
{
    uint32_t bh[2][4];
    ldm4(bh[0], abase + (uint32_t)RBASE);

    #pragma unroll
    for (int np = 0; np < 4; np++) {
        uint32_t DA[2][2][2], DB[2][2][2];
        #pragma unroll
        for (int b = 0; b < 2; b++)
            #pragma unroll
            for (int nt = 0; nt < 2; nt++) {
                DA[b][nt][0] = 0u; DA[b][nt][1] = 0u;
                DB[b][nt][0] = 0u; DB[b][nt][1] = 0u;
            }
        #pragma unroll
        for (int kt = 0; kt < KT; kt++) {
            const int idx = np * KT + kt;
            if (idx + 1 < 4 * KT) {
                const int np1 = (idx + 1) / KT, kt1 = (idx + 1) % KT;
                ldm4(bh[(idx + 1) & 1],
                     abase + (uint32_t)(RBASE + np1 * 16 * STRIDE + kt1 * 32));
            }
            const uint32_t* cur = bh[idx & 1];
            #pragma unroll
            for (int b = 0; b < 2; b++) {
                mma16816h(DA[b][0], ainA[b][kt], cur[0], cur[1]);
                mma16816h(DA[b][1], ainA[b][kt], cur[2], cur[3]);
                mma16816h(DB[b][0], ainB[b][kt], cur[0], cur[1]);
                mma16816h(DB[b][1], ainB[b][kt], cur[2], cur[3]);
            }
        }
        #pragma unroll
        for (int b = 0; b < 2; b++) {
            aoutA[b][np][0] = relu2(DA[b][0][0]);
            aoutA[b][np][1] = relu2(DA[b][0][1]);
            aoutA[b][np][2] = relu2(DA[b][1][0]);
            aoutA[b][np][3] = relu2(DA[b][1][1]);
            aoutB[b][np][0] = relu2(DB[b][0][0]);
            aoutB[b][np][1] = relu2(DB[b][0][1]);
            aoutB[b][np][2] = relu2(DB[b][1][0]);
            aoutB[b][np][3] = relu2(DB[b][1][1]);
        }
    }
}

// store W[K][N] (row-major) transposed into padded rows, fp16
__device__ __forceinline__ void fill_w(const float* __restrict__ W, int K, int N,
                                       int rbase, int stride, char* smem, int tid)
{
    char* wdst = smem + rbase;
    for (int idx = tid; idx < K * N; idx += TPB) {
        int k = idx / N, nn = idx % N;
        __half hb = __float2half(W[idx]);
        *reinterpret_cast<uint16_t*>(wdst + nn * stride + 2 * k) =
            *reinterpret_cast<uint16_t*>(&hb);
    }
}
// wc0 geo rows only: src k 3..17 (g1..g15) -> kd 1..15 in K=16 region. kd0 stays 0.
__device__ __forceinline__ void fill_wc0_geo(const float* __restrict__ W, char* smem, int tid)
{
    char* wdst = smem + RB_C0;
    for (int idx = tid; idx < 15 * 64; idx += TPB) {
        int j = idx / 64, nn = idx % 64;          // j = 0..14 -> src row 3+j, kd = 1+j
        __half hb = __float2half(W[(3 + j) * 64 + nn]);
        *reinterpret_cast<uint16_t*>(wdst + nn * ST16 + 2 * (1 + j)) =
            *reinterpret_cast<uint16_t*>(&hb);
    }
}

__global__ void __launch_bounds__(TPB, 2) nerf_hmma_kernel(
    const float* __restrict__ x,
    const float* __restrict__ ws0, const float* __restrict__ ws1,
    const float* __restrict__ ws2, const float* __restrict__ wc0,
    const float* __restrict__ wc1, const float* __restrict__ wc2,
    const float* __restrict__ wc3,
    float* __restrict__ out, int n)
{
    extern __shared__ char sm[];
    const uint32_t smb = smem_u32(sm);
    const int tid  = threadIdx.x;
    const int wid  = tid >> 5;
    const int lane = tid & 31;
    const int g4   = lane >> 2;
    const int m4   = lane & 3;

    for (int t = tid; t < WT_BYTES / 4; t += TPB)
        reinterpret_cast<uint32_t*>(sm)[t] = 0u;
    __syncthreads();
    fill_w(ws1, 64, 64, RB_S1, ST64, sm, tid);
    fill_w(ws2, 64, 16, RB_S2, ST64, sm, tid);
    fill_wc0_geo(wc0, sm, tid);
    fill_w(wc1, 64, 64, RB_C1, ST64, sm, tid);
    fill_w(wc2, 64, 64, RB_C2, ST64, sm, tid);
    fill_w(wc3, 64,  3, RB_C3, ST64, sm, tid);
    // fp32 stashes: ws0 [3][64]; wc0 view rows 0..2 [3][64]
    for (int t = tid; t < 192; t += TPB) {
        reinterpret_cast<float*>(sm + SM_WS0F)[t] = ws0[t];
        reinterpret_cast<float*>(sm + SM_WVF)[t]  = wc0[t];
    }
    __syncthreads();

    // per-lane ldmatrix base addresses
    const int mm = lane >> 3, rr = lane & 7;
    const int qrow = ((mm >= 2) ? 8 : 0) + rr;
    const uint32_t tsel = (mm & 1) ? 16u : 0u;
    const uint32_t a48  = smb + (uint32_t)(qrow * ST16) + tsel;
    const uint32_t a144 = smb + (uint32_t)(qrow * ST64) + tsel;
    const uint32_t a2   = smb + (uint32_t)(rr   * ST64) + tsel;   // ldm2 (C3)

    const float2* ws0f2 = reinterpret_cast<const float2*>(sm + SM_WS0F); // [3][32] f2
    const float2* wvf2  = reinterpret_cast<const float2*>(sm + SM_WVF);

    float* outbA = reinterpret_cast<float*>(sm + SM_OUT) + wid * (2 * 32 * 5);
    float* outbB = outbA + 32 * 5;

    const int ntiles = n / TILE;
    const int half   = ntiles >> 1;

    // ---- prefetch first pair's x ----
    float2 pA0, pA1, pA2, pB0, pB1, pB2;
    int tile = blockIdx.x;
    if (tile < half) {
        const float* xa = x + (size_t)(tile * TILE + wid * 32 + lane) * 6;
        pA0 = *reinterpret_cast<const float2*>(xa);
        pA1 = *reinterpret_cast<const float2*>(xa + 2);
        pA2 = *reinterpret_cast<const float2*>(xa + 4);
        const float* xb = x + (size_t)((tile + half) * TILE + wid * 32 + lane) * 6;
        pB0 = *reinterpret_cast<const float2*>(xb);
        pB1 = *reinterpret_cast<const float2*>(xb + 2);
        pB2 = *reinterpret_cast<const float2*>(xb + 4);
    }

    #pragma unroll 1
    for (; tile < half; tile += gridDim.x) {
        const int rowA = tile * TILE + wid * 32;
        const int rowB = (tile + half) * TILE + wid * 32;

        const uint32_t wA0 = pack2(pA0.x, pA0.y), wA1 = pack2(pA1.x, 0.0f);
        const uint32_t wA8 = pack2(pA1.y, pA2.x), wA9 = pack2(pA2.y, 0.0f);
        const uint32_t wB0 = pack2(pB0.x, pB0.y), wB1 = pack2(pB1.x, 0.0f);
        const uint32_t wB8 = pack2(pB1.y, pB2.x), wB9 = pack2(pB2.y, 0.0f);

        const int tnext = tile + gridDim.x;
        if (tnext < half) {
            const float* xa = x + (size_t)(tnext * TILE + wid * 32 + lane) * 6;
            pA0 = *reinterpret_cast<const float2*>(xa);
            pA1 = *reinterpret_cast<const float2*>(xa + 2);
            pA2 = *reinterpret_cast<const float2*>(xa + 4);
            const float* xb = x + (size_t)((tnext + half) * TILE + wid * 32 + lane) * 6;
            pB0 = *reinterpret_cast<const float2*>(xb);
            pB1 = *reinterpret_cast<const float2*>(xb + 2);
            pB2 = *reinterpret_cast<const float2*>(xb + 4);
        }

        uint32_t A0a[2][4][4], A1a[2][4][4], A0b[2][4][4], A1b[2][4][4];

        // ======== S0: 3 -> 64 entirely SCALAR (fp32 FMA, fp32 weights) ========
        {
            // gather x (fp16-quantized, as MMA path used) for rows r0/r1 per b, both tiles
            float xA[2][2][3], xB[2][2][3];
            #pragma unroll
            for (int b = 0; b < 2; b++) {
                int r0 = b*16 + g4, r1 = r0 + 8;
                #pragma unroll
                for (int rsel = 0; rsel < 2; rsel++) {
                    int src = rsel ? r1 : r0;
                    float2 fa = h2f(shfl_u(wA0, src));
                    xA[b][rsel][0] = fa.x; xA[b][rsel][1] = fa.y;
                    xA[b][rsel][2] = h2f(shfl_u(wA1, src)).x;
                    float2 fb = h2f(shfl_u(wB0, src));
                    xB[b][rsel][0] = fb.x; xB[b][rsel][1] = fb.y;
                    xB[b][rsel][2] = h2f(shfl_u(wB1, src)).x;
                }
            }
            #pragma unroll
            for (int np = 0; np < 4; np++) {
                const int ci = 8*np + m4;       // float2 index of col pair (2m4 + 16np)
                float2 w0p = ws0f2[ci],      w1p = ws0f2[32 + ci],  w2p = ws0f2[64 + ci];
                float2 w0q = ws0f2[ci + 4],  w1q = ws0f2[36 + ci],  w2q = ws0f2[68 + ci];
                #pragma unroll
                for (int b = 0; b < 2; b++)
                    #pragma unroll
                    for (int rsel = 0; rsel < 2; rsel++) {
                        const float* xa = xA[b][rsel];
                        float h0 = fmaf(xa[0], w0p.x, fmaf(xa[1], w1p.x, xa[2] * w2p.x));
                        float h1 = fmaf(xa[0], w0p.y, fmaf(xa[1], w1p.y, xa[2] * w2p.y));
                        float h2 = fmaf(xa[0], w0q.x, fmaf(xa[1], w1q.x, xa[2] * w2q.x));
                        float h3 = fmaf(xa[0], w0q.y, fmaf(xa[1], w1q.y, xa[2] * w2q.y));
                        A1a[b][np][rsel]     = relu2(pack2(h0, h1));
                        A1a[b][np][2 + rsel] = relu2(pack2(h2, h3));
                        const float* xb = xB[b][rsel];
                        float g0 = fmaf(xb[0], w0p.x, fmaf(xb[1], w1p.x, xb[2] * w2p.x));
                        float g1 = fmaf(xb[0], w0p.y, fmaf(xb[1], w1p.y, xb[2] * w2p.y));
                        float g2 = fmaf(xb[0], w0q.x, fmaf(xb[1], w1q.x, xb[2] * w2q.x));
                        float g3 = fmaf(xb[0], w0q.y, fmaf(xb[1], w1q.y, xb[2] * w2q.y));
                        A1b[b][np][rsel]     = relu2(pack2(g0, g1));
                        A1b[b][np][2 + rsel] = relu2(pack2(g2, g3));
                    }
            }
        }

        // ---- S1: 64 -> 64 (dual-tile fused) ----
        layer_h2<4, ST64, RB_S1>(a144, A1a, A1b, A0a, A0b);

        // ---- S2: 64 -> 16 (fp32 acc, no relu), dual-tile fused ----
        float CsA[2][2][4], CsB[2][2][4];
        {
            #pragma unroll
            for (int b = 0; b < 2; b++)
                #pragma unroll
                for (int j = 0; j < 2; j++)
                    #pragma unroll
                    for (int i = 0; i < 4; i++) { CsA[b][j][i] = 0.0f; CsB[b][j][i] = 0.0f; }
            uint32_t bh[2][4];
            ldm4(bh[0], a144 + (uint32_t)RB_S2);
            #pragma unroll
            for (int kt = 0; kt < 4; kt++) {
                if (kt + 1 < 4)
                    ldm4(bh[(kt + 1) & 1], a144 + (uint32_t)(RB_S2 + (kt + 1) * 32));
                const uint32_t* cur = bh[kt & 1];
                #pragma unroll
                for (int b = 0; b < 2; b++) {
                    mma16816(CsA[b][0], A0a[b][kt], cur[0], cur[1]);
                    mma16816(CsA[b][1], A0a[b][kt], cur[2], cur[3]);
                    mma16816(CsB[b][0], A0b[b][kt], cur[0], cur[1]);
                    mma16816(CsB[b][1], A0b[b][kt], cur[2], cur[3]);
                }
            }
        }

        // sigma
        #pragma unroll
        for (int b = 0; b < 2; b++) {
            if (m4 == 0) {
                int r0 = b*16 + g4, r1 = r0 + 8;
                float a0 = CsA[b][0][0], a2v = CsA[b][0][2];
                outbA[r0*5 + 3] = fmaxf(a0, 0.f) + log1pf(expf(-fabsf(a0)));
                outbA[r1*5 + 3] = fmaxf(a2v, 0.f) + log1pf(expf(-fabsf(a2v)));
                float b0v = CsB[b][0][0], b2v = CsB[b][0][2];
                outbB[r0*5 + 3] = fmaxf(b0v, 0.f) + log1pf(expf(-fabsf(b0v)));
                outbB[r1*5 + 3] = fmaxf(b2v, 0.f) + log1pf(expf(-fabsf(b2v)));
            }
        }

        // ---- C0 A frags (kt0 only): in-lane repack of S2 C-frags ----
        #pragma unroll
        for (int b = 0; b < 2; b++) {
            A0a[b][0][0] = pack2(CsA[b][0][0], CsA[b][0][1]);
            A0a[b][0][1] = pack2(CsA[b][0][2], CsA[b][0][3]);
            A0a[b][0][2] = pack2(CsA[b][1][0], CsA[b][1][1]);
            A0a[b][0][3] = pack2(CsA[b][1][2], CsA[b][1][3]);
            A0b[b][0][0] = pack2(CsB[b][0][0], CsB[b][0][1]);
            A0b[b][0][1] = pack2(CsB[b][0][2], CsB[b][0][3]);
            A0b[b][0][2] = pack2(CsB[b][1][0], CsB[b][1][1]);
            A0b[b][0][3] = pack2(CsB[b][1][2], CsB[b][1][3]);
        }

        // ======== C0: 16(geo) -> 64 MMA with views preloaded into D ========
        {
            // views fp32 per (b,row), both tiles
            float vA[2][2][3], vB[2][2][3];
            #pragma unroll
            for (int b = 0; b < 2; b++) {
                int r0 = b*16 + g4, r1 = r0 + 8;
                #pragma unroll
                for (int rsel = 0; rsel < 2; rsel++) {
                    int src = rsel ? r1 : r0;
                    float2 fa = h2f(shfl_u(wA8, src));
                    vA[b][rsel][0] = fa.x; vA[b][rsel][1] = fa.y;
                    vA[b][rsel][2] = h2f(shfl_u(wA9, src)).x;
                    float2 fb = h2f(shfl_u(wB8, src));
                    vB[b][rsel][0] = fb.x; vB[b][rsel][1] = fb.y;
                    vB[b][rsel][2] = h2f(shfl_u(wB9, src)).x;
                }
            }
            uint32_t bh[2][4];
            ldm4(bh[0], a48 + (uint32_t)RB_C0);
            #pragma unroll
            for (int np = 0; np < 4; np++) {
                if (np + 1 < 4)
                    ldm4(bh[(np + 1) & 1], a48 + (uint32_t)(RB_C0 + (np + 1) * 16 * ST16));
                uint32_t DA[2][2][2], DB[2][2][2];
                // D-init = views' contribution (fp32 dot -> fp16 pack)
                #pragma unroll
                for (int nt = 0; nt < 2; nt++) {
                    const int ci = 8*np + 4*nt + m4;      // float2 index of col pair
                    float2 w0p = wvf2[ci], w1p = wvf2[32 + ci], w2p = wvf2[64 + ci];
                    #pragma unroll
                    for (int b = 0; b < 2; b++)
                        #pragma unroll
                        for (int rsel = 0; rsel < 2; rsel++) {
                            const float* va = vA[b][rsel];
                            DA[b][nt][rsel] = pack2(
                                fmaf(va[0], w0p.x, fmaf(va[1], w1p.x, va[2] * w2p.x)),
                                fmaf(va[0], w0p.y, fmaf(va[1], w1p.y, va[2] * w2p.y)));
                            const float* vb = vB[b][rsel];
                            DB[b][nt][rsel] = pack2(
                                fmaf(vb[0], w0p.x, fmaf(vb[1], w1p.x, vb[2] * w2p.x)),
                                fmaf(vb[0], w0p.y, fmaf(vb[1], w1p.y, vb[2] * w2p.y)));
                        }
                }
                const uint32_t* cur = bh[np & 1];
                #pragma unroll
                for (int b = 0; b < 2; b++) {
                    mma16816h(DA[b][0], A0a[b][0], cur[0], cur[1]);
                    mma16816h(DA[b][1], A0a[b][0], cur[2], cur[3]);
                    mma16816h(DB[b][0], A0b[b][0], cur[0], cur[1]);
                    mma16816h(DB[b][1], A0b[b][0], cur[2], cur[3]);
                }
                #pragma unroll
                for (int b = 0; b < 2; b++) {
                    A1a[b][np][0] = relu2(DA[b][0][0]);
                    A1a[b][np][1] = relu2(DA[b][0][1]);
                    A1a[b][np][2] = relu2(DA[b][1][0]);
                    A1a[b][np][3] = relu2(DA[b][1][1]);
                    A1b[b][np][0] = relu2(DB[b][0][0]);
                    A1b[b][np][1] = relu2(DB[b][0][1]);
                    A1b[b][np][2] = relu2(DB[b][1][0]);
                    A1b[b][np][3] = relu2(DB[b][1][1]);
                }
            }
        }

        // ---- C1, C2: 64 -> 64 (dual-tile fused) ----
        layer_h2<4, ST64, RB_C1>(a144, A1a, A1b, A0a, A0b);
        layer_h2<4, ST64, RB_C2>(a144, A0a, A0b, A1a, A1b);

        // ---- C3: 64 -> 3 (fp32 acc, N padded to 8) ----
        {
            float CcA[2][4], CcB[2][4];
            #pragma unroll
            for (int b = 0; b < 2; b++)
                #pragma unroll
                for (int i = 0; i < 4; i++) { CcA[b][i] = 0.0f; CcB[b][i] = 0.0f; }
            uint32_t bh[2][2];
            ldm2(bh[0], a2 + (uint32_t)RB_C3);
            #pragma unroll
            for (int kt = 0; kt < 4; kt++) {
                if (kt + 1 < 4)
                    ldm2(bh[(kt + 1) & 1], a2 + (uint32_t)(RB_C3 + (kt + 1) * 32));
                const uint32_t* cur = bh[kt & 1];
                #pragma unroll
                for (int b = 0; b < 2; b++) {
                    mma16816(CcA[b], A1a[b][kt], cur[0], cur[1]);
                    mma16816(CcB[b], A1b[b][kt], cur[0], cur[1]);
                }
            }
            #pragma unroll
            for (int b = 0; b < 2; b++) {
                int r0 = b*16 + g4, r1 = r0 + 8;
                if (m4 == 0) {
                    outbA[r0*5+0] = CcA[b][0]; outbA[r0*5+1] = CcA[b][1];
                    outbA[r1*5+0] = CcA[b][2]; outbA[r1*5+1] = CcA[b][3];
                    outbB[r0*5+0] = CcB[b][0]; outbB[r0*5+1] = CcB[b][1];
                    outbB[r1*5+0] = CcB[b][2]; outbB[r1*5+1] = CcB[b][3];
                } else if (m4 == 1) {
                    outbA[r0*5+2] = CcA[b][0];
                    outbA[r1*5+2] = CcA[b][2];
                    outbB[r0*5+2] = CcB[b][0];
                    outbB[r1*5+2] = CcB[b][2];
                }
            }
        }
        __syncwarp();

        // ---- final stores ----
        {
            float4 rA;
            rA.x = outbA[lane*5+0]; rA.y = outbA[lane*5+1];
            rA.z = outbA[lane*5+2]; rA.w = outbA[lane*5+3];
            reinterpret_cast<float4*>(out)[rowA + lane] = rA;
            float4 rB;
            rB.x = outbB[lane*5+0]; rB.y = outbB[lane*5+1];
            rB.z = outbB[lane*5+2]; rB.w = outbB[lane*5+3];
            reinterpret_cast<float4*>(out)[rowB + lane] = rB;
        }
        __syncwarp();
    }
}

extern "C" void kernel_launch(void* const* d_in, const int* in_sizes, int n_in,
                              void* d_out, int out_size) {
    const float* x   = (const float*)d_in[0];
    const float* ws0 = (const float*)d_in[1];
    const float* ws1 = (const float*)d_in[2];
    const float* ws2 = (const float*)d_in[3];
    const float* wc0 = (const float*)d_in[4];
    const float* wc1 = (const float*)d_in[5];
    const float* wc2 = (const float*)d_in[6];
    const float* wc3 = (const float*)d_in[7];
    float* out = (float*)d_out;

    int n = in_sizes[0] / 6;
    int ntiles = n / TILE;
    int half = ntiles >> 1;

    cudaFuncSetAttribute(nerf_hmma_kernel,
                         cudaFuncAttributeMaxDynamicSharedMemorySize, SMEM_TOTAL);
    int grid = 296;                      // 2 persistent CTAs per SM
    if (grid > half) grid = half;
    nerf_hmma_kernel<<<grid, TPB, SMEM_TOTAL>>>(x, ws0, ws1, ws2, wc0, wc1, wc2, wc3, out, n);
}

// round 16
// speedup vs baseline: 1.0253x; 1.0253x over previous
#include <cuda_runtime.h>
#include <cuda_fp16.h>
#include <cstdint>

constexpr int TPB  = 128;   // 4 warps, each owns M=32 rows of TWO tiles
constexpr int TILE = 128;

// ---- weight SMEM: per-region row strides ≡ 16·odd (mod 128) -> ldmatrix
// conflict-free, linear addressing (SASS immediate offsets).
constexpr int ST_S0 = 48;    // K=16 (32B data)
constexpr int ST_C0 = 80;    // K=32 (64B data)
constexpr int ST_64 = 144;   // K=64 (128B data)

constexpr int RB_S0 = 0;                        // 64 rows x 48
constexpr int RB_S1 = RB_S0 + 64*ST_S0;         // 64 x 144
constexpr int RB_S2 = RB_S1 + 64*ST_64;         // 16 x 144
constexpr int RB_C0 = RB_S2 + 16*ST_64;         // 64 x 80
constexpr int RB_C1 = RB_C0 + 64*ST_C0;         // 64 x 144
constexpr int RB_C2 = RB_C1 + 64*ST_64;         // 64 x 144
constexpr int RB_C3 = RB_C2 + 64*ST_64;         // 8 x 144
constexpr int WT_BYTES = RB_C3 + 8*ST_64;       // 39296

constexpr int SM_OUT = WT_BYTES;                // 4w * 2tiles * 32r * 5 f32
constexpr int SMEM_TOTAL = SM_OUT + 4*2*32*5*4; // 44416 -> 2 CTAs/SM

// ---------------- PTX helpers ----------------
__device__ __forceinline__ uint32_t smem_u32(const void* p) {
    uint32_t a; asm("{ .reg .u64 t; cvta.to.shared.u64 t, %1; cvt.u32.u64 %0, t; }" : "=r"(a) : "l"(p));
    return a;
}
__device__ __forceinline__ void mma16816(float c[4], const uint32_t a[4], uint32_t b0, uint32_t b1) {
    asm volatile("mma.sync.aligned.m16n8k16.row.col.f32.f16.f16.f32 "
        "{%0,%1,%2,%3},{%4,%5,%6,%7},{%8,%9},{%0,%1,%2,%3};"
        : "+f"(c[0]), "+f"(c[1]), "+f"(c[2]), "+f"(c[3])
        : "r"(a[0]), "r"(a[1]), "r"(a[2]), "r"(a[3]), "r"(b0), "r"(b1));
}
__device__ __forceinline__ void mma16816h(uint32_t d[2], const uint32_t a[4], uint32_t b0, uint32_t b1) {
    asm volatile("mma.sync.aligned.m16n8k16.row.col.f16.f16.f16.f16 "
        "{%0,%1},{%2,%3,%4,%5},{%6,%7},{%0,%1};"
        : "+r"(d[0]), "+r"(d[1])
        : "r"(a[0]), "r"(a[1]), "r"(a[2]), "r"(a[3]), "r"(b0), "r"(b1));
}
// K=8 fp16-acc MMA: for zero-padded K tiles (S0, C0 views) -- half the MAC work.
__device__ __forceinline__ void mma16808h(uint32_t d[2], uint32_t a0, uint32_t a1, uint32_t b0) {
    asm volatile("mma.sync.aligned.m16n8k8.row.col.f16.f16.f16.f16 "
        "{%0,%1},{%2,%3},{%4},{%0,%1};"
        : "+r"(d[0]), "+r"(d[1])
        : "r"(a0), "r"(a1), "r"(b0));
}
__device__ __forceinline__ void ldm4(uint32_t r[4], uint32_t addr) {
    asm volatile("ldmatrix.sync.aligned.m8n8.x4.shared.b16 {%0,%1,%2,%3}, [%4];"
        : "=r"(r[0]), "=r"(r[1]), "=r"(r[2]), "=r"(r[3]) : "r"(addr));
}
__device__ __forceinline__ void ldm2(uint32_t r[2], uint32_t addr) {
    asm volatile("ldmatrix.sync.aligned.m8n8.x2.shared.b16 {%0,%1}, [%2];"
        : "=r"(r[0]), "=r"(r[1]) : "r"(addr));
}
__device__ __forceinline__ uint32_t pack2(float f0, float f1) {
    uint32_t h;
    asm("cvt.rn.f16x2.f32 %0, %1, %2;" : "=r"(h) : "f"(f1), "f"(f0));
    return h;
}
__device__ __forceinline__ uint32_t relu2(uint32_t v) {
    uint32_t r;
    asm("max.f16x2 %0, %1, %2;" : "=r"(r) : "r"(v), "r"(0u));
    return r;
}
__device__ __forceinline__ uint32_t shfl_u(uint32_t v, int src) {
    return __shfl_sync(0xffffffffu, v, src);
}

// ---- fused dual-tile hidden layer, fp16 acc: ONE ldm4 feeds BOTH tiles' MMAs ----
template<int KT, int STRIDE, int RBASE>
__device__ __forceinline__ void layer_h2(uint32_t abase,
                                         const uint32_t ainA[2][4][4],
                                         const uint32_t ainB[2][4][4],
                                         uint32_t aoutA[2][4][4],
                                         uint32_t aoutB[2][4][4])
{
    uint32_t bh[2][4];
    ldm4(bh[0], abase + (uint32_t)RBASE);

    #pragma unroll
    for (int np = 0; np < 4; np++) {
        uint32_t DA[2][2][2], DB[2][2][2];
        #pragma unroll
        for (int b = 0; b < 2; b++)
            #pragma unroll
            for (int nt = 0; nt < 2; nt++) {
                DA[b][nt][0] = 0u; DA[b][nt][1] = 0u;
                DB[b][nt][0] = 0u; DB[b][nt][1] = 0u;
            }
        #pragma unroll
        for (int kt = 0; kt < KT; kt++) {
            const int idx = np * KT + kt;
            if (idx + 1 < 4 * KT) {
                const int np1 = (idx + 1) / KT, kt1 = (idx + 1) % KT;
                ldm4(bh[(idx + 1) & 1],
                     abase + (uint32_t)(RBASE + np1 * 16 * STRIDE + kt1 * 32));
            }
            const uint32_t* cur = bh[idx & 1];
            #pragma unroll
            for (int b = 0; b < 2; b++) {
                mma16816h(DA[b][0], ainA[b][kt], cur[0], cur[1]);
                mma16816h(DA[b][1], ainA[b][kt], cur[2], cur[3]);
                mma16816h(DB[b][0], ainB[b][kt], cur[0], cur[1]);
                mma16816h(DB[b][1], ainB[b][kt], cur[2], cur[3]);
            }
        }
        #pragma unroll
        for (int b = 0; b < 2; b++) {
            aoutA[b][np][0] = relu2(DA[b][0][0]);
            aoutA[b][np][1] = relu2(DA[b][0][1]);
            aoutA[b][np][2] = relu2(DA[b][1][0]);
            aoutA[b][np][3] = relu2(DA[b][1][1]);
            aoutB[b][np][0] = relu2(DB[b][0][0]);
            aoutB[b][np][1] = relu2(DB[b][0][1]);
            aoutB[b][np][2] = relu2(DB[b][1][0]);
            aoutB[b][np][3] = relu2(DB[b][1][1]);
        }
    }
}

// store W[K][N] (row-major) transposed into padded rows, fp16
__device__ __forceinline__ void fill_w(const float* __restrict__ W, int K, int N,
                                       int rbase, int stride, char* smem, int tid)
{
    char* wdst = smem + rbase;
    for (int idx = tid; idx < K * N; idx += TPB) {
        int k = idx / N, nn = idx % N;
        __half hb = __float2half(W[idx]);
        *reinterpret_cast<uint16_t*>(wdst + nn * stride + 2 * k) =
            *reinterpret_cast<uint16_t*>(&hb);
    }
}
// wc0 with permuted K rows: src 0..2 (views) -> k 16..18; src 3..17 (g1..g15) -> k 1..15.
__device__ __forceinline__ void fill_wc0(const float* __restrict__ W, char* smem, int tid)
{
    char* wdst = smem + RB_C0;
    for (int idx = tid; idx < 18 * 64; idx += TPB) {
        int k = idx / 64, nn = idx % 64;
        int kd = (k < 3) ? (16 + k) : (k - 2);
        __half hb = __float2half(W[idx]);
        *reinterpret_cast<uint16_t*>(wdst + nn * ST_C0 + 2 * kd) =
            *reinterpret_cast<uint16_t*>(&hb);
    }
}

__global__ void __launch_bounds__(TPB, 2) nerf_hmma_kernel(
    const float* __restrict__ x,
    const float* __restrict__ ws0, const float* __restrict__ ws1,
    const float* __restrict__ ws2, const float* __restrict__ wc0,
    const float* __restrict__ wc1, const float* __restrict__ wc2,
    const float* __restrict__ wc3,
    float* __restrict__ out, int n)
{
    extern __shared__ char sm[];
    const uint32_t smb = smem_u32(sm);
    const int tid  = threadIdx.x;
    const int wid  = tid >> 5;
    const int lane = tid & 31;
    const int g4   = lane >> 2;
    const int m4   = lane & 3;

    for (int t = tid; t < WT_BYTES / 4; t += TPB)
        reinterpret_cast<uint32_t*>(sm)[t] = 0u;
    __syncthreads();
    fill_w(ws0,  3, 64, RB_S0, ST_S0, sm, tid);
    fill_w(ws1, 64, 64, RB_S1, ST_64, sm, tid);
    fill_w(ws2, 64, 16, RB_S2, ST_64, sm, tid);
    fill_wc0(wc0, sm, tid);
    fill_w(wc1, 64, 64, RB_C1, ST_64, sm, tid);
    fill_w(wc2, 64, 64, RB_C2, ST_64, sm, tid);
    fill_w(wc3, 64,  3, RB_C3, ST_64, sm, tid);
    __syncthreads();

    // per-lane ldmatrix base addresses (one per stride class)
    const int mm = lane >> 3, rr = lane & 7;
    const int qrow = ((mm >= 2) ? 8 : 0) + rr;
    const uint32_t tsel = (mm & 1) ? 16u : 0u;
    const uint32_t a48  = smb + (uint32_t)(qrow * ST_S0) + tsel;
    const uint32_t a80  = smb + (uint32_t)(qrow * ST_C0) + tsel;
    const uint32_t a144 = smb + (uint32_t)(qrow * ST_64) + tsel;
    const uint32_t a2   = smb + (uint32_t)(rr   * ST_64) + tsel;   // ldm2 (C3)

    float* outbA = reinterpret_cast<float*>(sm + SM_OUT) + wid * (2 * 32 * 5);
    float* outbB = outbA + 32 * 5;

    const int ntiles = n / TILE;
    const int half   = ntiles >> 1;

    // ---- prefetch first pair's x ----
    float2 pA0, pA1, pA2, pB0, pB1, pB2;
    int tile = blockIdx.x;
    if (tile < half) {
        const float* xa = x + (size_t)(tile * TILE + wid * 32 + lane) * 6;
        pA0 = *reinterpret_cast<const float2*>(xa);
        pA1 = *reinterpret_cast<const float2*>(xa + 2);
        pA2 = *reinterpret_cast<const float2*>(xa + 4);
        const float* xb = x + (size_t)((tile + half) * TILE + wid * 32 + lane) * 6;
        pB0 = *reinterpret_cast<const float2*>(xb);
        pB1 = *reinterpret_cast<const float2*>(xb + 2);
        pB2 = *reinterpret_cast<const float2*>(xb + 4);
    }

    #pragma unroll 1
    for (; tile < half; tile += gridDim.x) {
        const int rowA = tile * TILE + wid * 32;
        const int rowB = (tile + half) * TILE + wid * 32;

        const uint32_t wA0 = pack2(pA0.x, pA0.y), wA1 = pack2(pA1.x, 0.0f);
        const uint32_t wA8 = pack2(pA1.y, pA2.x), wA9 = pack2(pA2.y, 0.0f);
        const uint32_t wB0 = pack2(pB0.x, pB0.y), wB1 = pack2(pB1.x, 0.0f);
        const uint32_t wB8 = pack2(pB1.y, pB2.x), wB9 = pack2(pB2.y, 0.0f);

        const int tnext = tile + gridDim.x;
        if (tnext < half) {
            const float* xa = x + (size_t)(tnext * TILE + wid * 32 + lane) * 6;
            pA0 = *reinterpret_cast<const float2*>(xa);
            pA1 = *reinterpret_cast<const float2*>(xa + 2);
            pA2 = *reinterpret_cast<const float2*>(xa + 4);
            const float* xb = x + (size_t)((tnext + half) * TILE + wid * 32 + lane) * 6;
            pB0 = *reinterpret_cast<const float2*>(xb);
            pB1 = *reinterpret_cast<const float2*>(xb + 2);
            pB2 = *reinterpret_cast<const float2*>(xb + 4);
        }

        uint32_t A0a[2][4][4], A1a[2][4][4], A0b[2][4][4], A1b[2][4][4];

        // ---- build S0 A frags via shfl (K=8 effective: pts in k0..2) ----
        #pragma unroll
        for (int b = 0; b < 2; b++) {
            int r0 = b*16 + g4, r1 = r0 + 8;
            uint32_t uA00 = shfl_u(wA0, r0), uA01 = shfl_u(wA1, r0);
            uint32_t uA10 = shfl_u(wA0, r1), uA11 = shfl_u(wA1, r1);
            A0a[b][0][0] = (m4 == 0) ? uA00 : (m4 == 1) ? uA01 : 0u;
            A0a[b][0][1] = (m4 == 0) ? uA10 : (m4 == 1) ? uA11 : 0u;
            A0a[b][0][2] = 0u; A0a[b][0][3] = 0u;
            uint32_t uB00 = shfl_u(wB0, r0), uB01 = shfl_u(wB1, r0);
            uint32_t uB10 = shfl_u(wB0, r1), uB11 = shfl_u(wB1, r1);
            A0b[b][0][0] = (m4 == 0) ? uB00 : (m4 == 1) ? uB01 : 0u;
            A0b[b][0][1] = (m4 == 0) ? uB10 : (m4 == 1) ? uB11 : 0u;
            A0b[b][0][2] = 0u; A0b[b][0][3] = 0u;
        }

        // ======== S0: 3 -> 64 via m16n8k8 (K=8 covers the 3 real dims) ========
        {
            uint32_t bh[2][4];
            ldm4(bh[0], a48 + (uint32_t)RB_S0);
            #pragma unroll
            for (int np = 0; np < 4; np++) {
                if (np + 1 < 4)
                    ldm4(bh[(np + 1) & 1], a48 + (uint32_t)(RB_S0 + (np + 1) * 16 * ST_S0));
                const uint32_t* cur = bh[np & 1];   // cur[0]=(n0,k0..7), cur[2]=(n8,k0..7)
                uint32_t DA[2][2][2], DB[2][2][2];
                #pragma unroll
                for (int b = 0; b < 2; b++)
                    #pragma unroll
                    for (int nt = 0; nt < 2; nt++) {
                        DA[b][nt][0] = 0u; DA[b][nt][1] = 0u;
                        DB[b][nt][0] = 0u; DB[b][nt][1] = 0u;
                    }
                #pragma unroll
                for (int b = 0; b < 2; b++) {
                    mma16808h(DA[b][0], A0a[b][0][0], A0a[b][0][1], cur[0]);
                    mma16808h(DA[b][1], A0a[b][0][0], A0a[b][0][1], cur[2]);
                    mma16808h(DB[b][0], A0b[b][0][0], A0b[b][0][1], cur[0]);
                    mma16808h(DB[b][1], A0b[b][0][0], A0b[b][0][1], cur[2]);
                }
                #pragma unroll
                for (int b = 0; b < 2; b++) {
                    A1a[b][np][0] = relu2(DA[b][0][0]);
                    A1a[b][np][1] = relu2(DA[b][0][1]);
                    A1a[b][np][2] = relu2(DA[b][1][0]);
                    A1a[b][np][3] = relu2(DA[b][1][1]);
                    A1b[b][np][0] = relu2(DB[b][0][0]);
                    A1b[b][np][1] = relu2(DB[b][0][1]);
                    A1b[b][np][2] = relu2(DB[b][1][0]);
                    A1b[b][np][3] = relu2(DB[b][1][1]);
                }
            }
        }

        // ---- S1: 64 -> 64 (dual-tile fused) ----
        layer_h2<4, ST_64, RB_S1>(a144, A1a, A1b, A0a, A0b);

        // ---- S2: 64 -> 16 (fp32 acc, no relu), dual-tile fused ----
        float CsA[2][2][4], CsB[2][2][4];
        {
            #pragma unroll
            for (int b = 0; b < 2; b++)
                #pragma unroll
                for (int j = 0; j < 2; j++)
                    #pragma unroll
                    for (int i = 0; i < 4; i++) { CsA[b][j][i] = 0.0f; CsB[b][j][i] = 0.0f; }
            uint32_t bh[2][4];
            ldm4(bh[0], a144 + (uint32_t)RB_S2);
            #pragma unroll
            for (int kt = 0; kt < 4; kt++) {
                if (kt + 1 < 4)
                    ldm4(bh[(kt + 1) & 1], a144 + (uint32_t)(RB_S2 + (kt + 1) * 32));
                const uint32_t* cur = bh[kt & 1];
                #pragma unroll
                for (int b = 0; b < 2; b++) {
                    mma16816(CsA[b][0], A0a[b][kt], cur[0], cur[1]);
                    mma16816(CsA[b][1], A0a[b][kt], cur[2], cur[3]);
                    mma16816(CsB[b][0], A0b[b][kt], cur[0], cur[1]);
                    mma16816(CsB[b][1], A0b[b][kt], cur[2], cur[3]);
                }
            }
        }

        // sigma (lane m4==0 holds col 0 for rows r0/r1), both tiles
        #pragma unroll
        for (int b = 0; b < 2; b++) {
            if (m4 == 0) {
                int r0 = b*16 + g4, r1 = r0 + 8;
                float a0 = CsA[b][0][0], a2v = CsA[b][0][2];
                outbA[r0*5 + 3] = fmaxf(a0, 0.f) + log1pf(expf(-fabsf(a0)));
                outbA[r1*5 + 3] = fmaxf(a2v, 0.f) + log1pf(expf(-fabsf(a2v)));
                float b0v = CsB[b][0][0], b2v = CsB[b][0][2];
                outbB[r0*5 + 3] = fmaxf(b0v, 0.f) + log1pf(expf(-fabsf(b0v)));
                outbB[r1*5 + 3] = fmaxf(b2v, 0.f) + log1pf(expf(-fabsf(b2v)));
            }
        }

        // ---- build C0 A frags: kt=0 in-lane repack of S2 C-frags; kt=1 views via shfl ----
        #pragma unroll
        for (int b = 0; b < 2; b++) {
            int r0 = b*16 + g4, r1 = r0 + 8;
            A0a[b][0][0] = pack2(CsA[b][0][0], CsA[b][0][1]);
            A0a[b][0][1] = pack2(CsA[b][0][2], CsA[b][0][3]);
            A0a[b][0][2] = pack2(CsA[b][1][0], CsA[b][1][1]);
            A0a[b][0][3] = pack2(CsA[b][1][2], CsA[b][1][3]);
            uint32_t vA00 = shfl_u(wA8, r0), vA01 = shfl_u(wA9, r0);
            uint32_t vA10 = shfl_u(wA8, r1), vA11 = shfl_u(wA9, r1);
            A0a[b][1][0] = (m4 == 0) ? vA00 : (m4 == 1) ? vA01 : 0u;
            A0a[b][1][1] = (m4 == 0) ? vA10 : (m4 == 1) ? vA11 : 0u;
            A0a[b][1][2] = 0u; A0a[b][1][3] = 0u;

            A0b[b][0][0] = pack2(CsB[b][0][0], CsB[b][0][1]);
            A0b[b][0][1] = pack2(CsB[b][0][2], CsB[b][0][3]);
            A0b[b][0][2] = pack2(CsB[b][1][0], CsB[b][1][1]);
            A0b[b][0][3] = pack2(CsB[b][1][2], CsB[b][1][3]);
            uint32_t vB00 = shfl_u(wB8, r0), vB01 = shfl_u(wB9, r0);
            uint32_t vB10 = shfl_u(wB8, r1), vB11 = shfl_u(wB9, r1);
            A0b[b][1][0] = (m4 == 0) ? vB00 : (m4 == 1) ? vB01 : 0u;
            A0b[b][1][1] = (m4 == 0) ? vB10 : (m4 == 1) ? vB11 : 0u;
            A0b[b][1][2] = 0u; A0b[b][1][3] = 0u;
        }

        // ======== C0: kt0 geo k16 MMA + kt1 views m16n8k8 ========
        {
            uint32_t bh[2][8];   // per step: [0..3]=kt0 mats, [4..7]=kt1 mats
            ldm4(bh[0],     a80 + (uint32_t)RB_C0);
            ldm4(bh[0] + 4, a80 + (uint32_t)(RB_C0 + 32));
            #pragma unroll
            for (int np = 0; np < 4; np++) {
                if (np + 1 < 4) {
                    ldm4(bh[(np + 1) & 1],     a80 + (uint32_t)(RB_C0 + (np + 1) * 16 * ST_C0));
                    ldm4(bh[(np + 1) & 1] + 4, a80 + (uint32_t)(RB_C0 + (np + 1) * 16 * ST_C0 + 32));
                }
                const uint32_t* c0 = bh[np & 1];
                const uint32_t* c1 = bh[np & 1] + 4;
                uint32_t DA[2][2][2], DB[2][2][2];
                #pragma unroll
                for (int b = 0; b < 2; b++)
                    #pragma unroll
                    for (int nt = 0; nt < 2; nt++) {
                        DA[b][nt][0] = 0u; DA[b][nt][1] = 0u;
                        DB[b][nt][0] = 0u; DB[b][nt][1] = 0u;
                    }
                #pragma unroll
                for (int b = 0; b < 2; b++) {
                    mma16816h(DA[b][0], A0a[b][0], c0[0], c0[1]);
                    mma16816h(DA[b][1], A0a[b][0], c0[2], c0[3]);
                    mma16816h(DB[b][0], A0b[b][0], c0[0], c0[1]);
                    mma16816h(DB[b][1], A0b[b][0], c0[2], c0[3]);
                }
                #pragma unroll
                for (int b = 0; b < 2; b++) {
                    mma16808h(DA[b][0], A0a[b][1][0], A0a[b][1][1], c1[0]);
                    mma16808h(DA[b][1], A0a[b][1][0], A0a[b][1][1], c1[2]);
                    mma16808h(DB[b][0], A0b[b][1][0], A0b[b][1][1], c1[0]);
                    mma16808h(DB[b][1], A0b[b][1][0], A0b[b][1][1], c1[2]);
                }
                #pragma unroll
                for (int b = 0; b < 2; b++) {
                    A1a[b][np][0] = relu2(DA[b][0][0]);
                    A1a[b][np][1] = relu2(DA[b][0][1]);
                    A1a[b][np][2] = relu2(DA[b][1][0]);
                    A1a[b][np][3] = relu2(DA[b][1][1]);
                    A1b[b][np][0] = relu2(DB[b][0][0]);
                    A1b[b][np][1] = relu2(DB[b][0][1]);
                    A1b[b][np][2] = relu2(DB[b][1][0]);
                    A1b[b][np][3] = relu2(DB[b][1][1]);
                }
            }
        }

        // ---- C1, C2: 64 -> 64 (dual-tile fused) ----
        layer_h2<4, ST_64, RB_C1>(a144, A1a, A1b, A0a, A0b);
        layer_h2<4, ST_64, RB_C2>(a144, A0a, A0b, A1a, A1b);

        // ---- C3: 64 -> 3 (fp32 acc, N padded to 8) ----
        {
            float CcA[2][4], CcB[2][4];
            #pragma unroll
            for (int b = 0; b < 2; b++)
                #pragma unroll
                for (int i = 0; i < 4; i++) { CcA[b][i] = 0.0f; CcB[b][i] = 0.0f; }
            uint32_t bh[2][2];
            ldm2(bh[0], a2 + (uint32_t)RB_C3);
            #pragma unroll
            for (int kt = 0; kt < 4; kt++) {
                if (kt + 1 < 4)
                    ldm2(bh[(kt + 1) & 1], a2 + (uint32_t)(RB_C3 + (kt + 1) * 32));
                const uint32_t* cur = bh[kt & 1];
                #pragma unroll
                for (int b = 0; b < 2; b++) {
                    mma16816(CcA[b], A1a[b][kt], cur[0], cur[1]);
                    mma16816(CcB[b], A1b[b][kt], cur[0], cur[1]);
                }
            }
            #pragma unroll
            for (int b = 0; b < 2; b++) {
                int r0 = b*16 + g4, r1 = r0 + 8;
                if (m4 == 0) {
                    outbA[r0*5+0] = CcA[b][0]; outbA[r0*5+1] = CcA[b][1];
                    outbA[r1*5+0] = CcA[b][2]; outbA[r1*5+1] = CcA[b][3];
                    outbB[r0*5+0] = CcB[b][0]; outbB[r0*5+1] = CcB[b][1];
                    outbB[r1*5+0] = CcB[b][2]; outbB[r1*5+1] = CcB[b][3];
                } else if (m4 == 1) {
                    outbA[r0*5+2] = CcA[b][0];
                    outbA[r1*5+2] = CcA[b][2];
                    outbB[r0*5+2] = CcB[b][0];
                    outbB[r1*5+2] = CcB[b][2];
                }
            }
        }
        __syncwarp();

        // ---- final stores ----
        {
            float4 rA;
            rA.x = outbA[lane*5+0]; rA.y = outbA[lane*5+1];
            rA.z = outbA[lane*5+2]; rA.w = outbA[lane*5+3];
            reinterpret_cast<float4*>(out)[rowA + lane] = rA;
            float4 rB;
            rB.x = outbB[lane*5+0]; rB.y = outbB[lane*5+1];
            rB.z = outbB[lane*5+2]; rB.w = outbB[lane*5+3];
            reinterpret_cast<float4*>(out)[rowB + lane] = rB;
        }
        __syncwarp();
    }
}

extern "C" void kernel_launch(void* const* d_in, const int* in_sizes, int n_in,
                              void* d_out, int out_size) {
    const float* x   = (const float*)d_in[0];
    const float* ws0 = (const float*)d_in[1];
    const float* ws1 = (const float*)d_in[2];
    const float* ws2 = (const float*)d_in[3];
    const float* wc0 = (const float*)d_in[4];
    const float* wc1 = (const float*)d_in[5];
    const float* wc2 = (const float*)d_in[6];
    const float* wc3 = (const float*)d_in[7];
    float* out = (float*)d_out;

    int n = in_sizes[0] / 6;
    int ntiles = n / TILE;
    int half = ntiles >> 1;

    cudaFuncSetAttribute(nerf_hmma_kernel,
                         cudaFuncAttributeMaxDynamicSharedMemorySize, SMEM_TOTAL);
    int grid = 296;                      // 2 persistent CTAs per SM
    if (grid > half) grid = half;
    nerf_hmma_kernel<<<grid, TPB, SMEM_TOTAL>>>(x, ws0, ws1, ws2, wc0, wc1, wc2, wc3, out, n);
}

// round 17
// speedup vs baseline: 1.0426x; 1.0169x over previous
#include <cuda_runtime.h>
#include <cuda_fp16.h>
#include <cstdint>

constexpr int TPB  = 128;   // 4 warps, each owns M=32 rows of TWO tiles
constexpr int TILE = 128;

// ---- weight SMEM: per-region row strides ≡ 16·odd (mod 128) -> ldmatrix
// conflict-free, linear addressing (SASS immediate offsets).
constexpr int ST_C0 = 80;    // K=32 (64B data)
constexpr int ST_64 = 144;   // K=64 (128B data)

constexpr int RB_S1 = 0;                        // 64 x 144
constexpr int RB_S2 = RB_S1 + 64*ST_64;         // 9216,  16 x 144
constexpr int RB_C0 = RB_S2 + 16*ST_64;         // 11520, 64 x 80
constexpr int RB_C1 = RB_C0 + 64*ST_C0;         // 16640, 64 x 144
constexpr int RB_C2 = RB_C1 + 64*ST_64;         // 25856, 64 x 144
constexpr int RB_C3 = RB_C2 + 64*ST_64;         // 35072, 8 x 144
constexpr int WT_BYTES = RB_C3 + 8*ST_64;       // 36224

constexpr int SM_WS0F = WT_BYTES;               // fp32 ws0 [3][64] = 768 B
constexpr int SM_XB   = SM_WS0F + 768;          // 4w * 2t * 32r * 4 f32 = 4096 B
constexpr int SM_OUT  = SM_XB + 4096;           // 4w * 2t * 32r * 5 f32 = 5120 B
constexpr int SMEM_TOTAL = SM_OUT + 5120;       // 46208 -> 2 CTAs/SM

// ---------------- PTX helpers ----------------
__device__ __forceinline__ uint32_t smem_u32(const void* p) {
    uint32_t a; asm("{ .reg .u64 t; cvta.to.shared.u64 t, %1; cvt.u32.u64 %0, t; }" : "=r"(a) : "l"(p));
    return a;
}
__device__ __forceinline__ void mma16816(float c[4], const uint32_t a[4], uint32_t b0, uint32_t b1) {
    asm volatile("mma.sync.aligned.m16n8k16.row.col.f32.f16.f16.f32 "
        "{%0,%1,%2,%3},{%4,%5,%6,%7},{%8,%9},{%0,%1,%2,%3};"
        : "+f"(c[0]), "+f"(c[1]), "+f"(c[2]), "+f"(c[3])
        : "r"(a[0]), "r"(a[1]), "r"(a[2]), "r"(a[3]), "r"(b0), "r"(b1));
}
__device__ __forceinline__ void mma16816h(uint32_t d[2], const uint32_t a[4], uint32_t b0, uint32_t b1) {
    asm volatile("mma.sync.aligned.m16n8k16.row.col.f16.f16.f16.f16 "
        "{%0,%1},{%2,%3,%4,%5},{%6,%7},{%0,%1};"
        : "+r"(d[0]), "+r"(d[1])
        : "r"(a[0]), "r"(a[1]), "r"(a[2]), "r"(a[3]), "r"(b0), "r"(b1));
}
__device__ __forceinline__ void ldm4(uint32_t r[4], uint32_t addr) {
    asm volatile("ldmatrix.sync.aligned.m8n8.x4.shared.b16 {%0,%1,%2,%3}, [%4];"
        : "=r"(r[0]), "=r"(r[1]), "=r"(r[2]), "=r"(r[3]) : "r"(addr));
}
__device__ __forceinline__ void ldm2(uint32_t r[2], uint32_t addr) {
    asm volatile("ldmatrix.sync.aligned.m8n8.x2.shared.b16 {%0,%1}, [%2];"
        : "=r"(r[0]), "=r"(r[1]) : "r"(addr));
}
__device__ __forceinline__ uint32_t pack2(float f0, float f1) {
    uint32_t h;
    asm("cvt.rn.f16x2.f32 %0, %1, %2;" : "=r"(h) : "f"(f1), "f"(f0));
    return h;
}
__device__ __forceinline__ uint32_t relu2(uint32_t v) {
    uint32_t r;
    asm("max.f16x2 %0, %1, %2;" : "=r"(r) : "r"(v), "r"(0u));
    return r;
}
__device__ __forceinline__ uint32_t shfl_u(uint32_t v, int src) {
    return __shfl_sync(0xffffffffu, v, src);
}

// ---- fused dual-tile hidden layer, fp16 acc: ONE ldm4 feeds BOTH tiles' MMAs ----
template<int KT, int STRIDE, int RBASE>
__device__ __forceinline__ void layer_h2(uint32_t abase,
                                         const uint32_t ainA[2][4][4],
                                         const uint32_t ainB[2][4][4],
                                         uint32_t aoutA[2][4][4],
                                         uint32_t aoutB[2][4][4])
{
    uint32_t bh[2][4];
    ldm4(bh[0], abase + (uint32_t)RBASE);

    #pragma unroll
    for (int np = 0; np < 4; np++) {
        uint32_t DA[2][2][2], DB[2][2][2];
        #pragma unroll
        for (int b = 0; b < 2; b++)
            #pragma unroll
            for (int nt = 0; nt < 2; nt++) {
                DA[b][nt][0] = 0u; DA[b][nt][1] = 0u;
                DB[b][nt][0] = 0u; DB[b][nt][1] = 0u;
            }
        #pragma unroll
        for (int kt = 0; kt < KT; kt++) {
            const int idx = np * KT + kt;
            if (idx + 1 < 4 * KT) {
                const int np1 = (idx + 1) / KT, kt1 = (idx + 1) % KT;
                ldm4(bh[(idx + 1) & 1],
                     abase + (uint32_t)(RBASE + np1 * 16 * STRIDE + kt1 * 32));
            }
            const uint32_t* cur = bh[idx & 1];
            #pragma unroll
            for (int b = 0; b < 2; b++) {
                mma16816h(DA[b][0], ainA[b][kt], cur[0], cur[1]);
                mma16816h(DA[b][1], ainA[b][kt], cur[2], cur[3]);
                mma16816h(DB[b][0], ainB[b][kt], cur[0], cur[1]);
                mma16816h(DB[b][1], ainB[b][kt], cur[2], cur[3]);
            }
        }
        #pragma unroll
        for (int b = 0; b < 2; b++) {
            aoutA[b][np][0] = relu2(DA[b][0][0]);
            aoutA[b][np][1] = relu2(DA[b][0][1]);
            aoutA[b][np][2] = relu2(DA[b][1][0]);
            aoutA[b][np][3] = relu2(DA[b][1][1]);
            aoutB[b][np][0] = relu2(DB[b][0][0]);
            aoutB[b][np][1] = relu2(DB[b][0][1]);
            aoutB[b][np][2] = relu2(DB[b][1][0]);
            aoutB[b][np][3] = relu2(DB[b][1][1]);
        }
    }
}

// store W[K][N] (row-major) transposed into padded rows, fp16
__device__ __forceinline__ void fill_w(const float* __restrict__ W, int K, int N,
                                       int rbase, int stride, char* smem, int tid)
{
    char* wdst = smem + rbase;
    for (int idx = tid; idx < K * N; idx += TPB) {
        int k = idx / N, nn = idx % N;
        __half hb = __float2half(W[idx]);
        *reinterpret_cast<uint16_t*>(wdst + nn * stride + 2 * k) =
            *reinterpret_cast<uint16_t*>(&hb);
    }
}
// wc0 with permuted K rows: src 0..2 (views) -> k 16..18; src 3..17 (g1..g15) -> k 1..15.
__device__ __forceinline__ void fill_wc0(const float* __restrict__ W, char* smem, int tid)
{
    char* wdst = smem + RB_C0;
    for (int idx = tid; idx < 18 * 64; idx += TPB) {
        int k = idx / 64, nn = idx % 64;
        int kd = (k < 3) ? (16 + k) : (k - 2);
        __half hb = __float2half(W[idx]);
        *reinterpret_cast<uint16_t*>(wdst + nn * ST_C0 + 2 * kd) =
            *reinterpret_cast<uint16_t*>(&hb);
    }
}

__global__ void __launch_bounds__(TPB, 2) nerf_hmma_kernel(
    const float* __restrict__ x,
    const float* __restrict__ ws0, const float* __restrict__ ws1,
    const float* __restrict__ ws2, const float* __restrict__ wc0,
    const float* __restrict__ wc1, const float* __restrict__ wc2,
    const float* __restrict__ wc3,
    float* __restrict__ out, int n)
{
    extern __shared__ char sm[];
    const uint32_t smb = smem_u32(sm);
    const int tid  = threadIdx.x;
    const int wid  = tid >> 5;
    const int lane = tid & 31;
    const int g4   = lane >> 2;
    const int m4   = lane & 3;

    for (int t = tid; t < WT_BYTES / 4; t += TPB)
        reinterpret_cast<uint32_t*>(sm)[t] = 0u;
    __syncthreads();
    fill_w(ws1, 64, 64, RB_S1, ST_64, sm, tid);
    fill_w(ws2, 64, 16, RB_S2, ST_64, sm, tid);
    fill_wc0(wc0, sm, tid);
    fill_w(wc1, 64, 64, RB_C1, ST_64, sm, tid);
    fill_w(wc2, 64, 64, RB_C2, ST_64, sm, tid);
    fill_w(wc3, 64,  3, RB_C3, ST_64, sm, tid);
    for (int t = tid; t < 192; t += TPB)
        reinterpret_cast<float*>(sm + SM_WS0F)[t] = ws0[t];   // fp32 ws0 stash
    __syncthreads();

    // per-lane ldmatrix base addresses (one per stride class)
    const int mm = lane >> 3, rr = lane & 7;
    const int qrow = ((mm >= 2) ? 8 : 0) + rr;
    const uint32_t tsel = (mm & 1) ? 16u : 0u;
    const uint32_t a80  = smb + (uint32_t)(qrow * ST_C0) + tsel;
    const uint32_t a144 = smb + (uint32_t)(qrow * ST_64) + tsel;
    const uint32_t a2   = smb + (uint32_t)(rr   * ST_64) + tsel;   // ldm2 (C3)

    const float2* ws0f2 = reinterpret_cast<const float2*>(sm + SM_WS0F); // [3][32] f2

    // per-warp staging
    float* xbA   = reinterpret_cast<float*>(sm + SM_XB)  + wid * (2 * 32 * 4);
    float* xbB   = xbA + 32 * 4;
    float* outbA = reinterpret_cast<float*>(sm + SM_OUT) + wid * (2 * 32 * 5);
    float* outbB = outbA + 32 * 5;

    const int ntiles = n / TILE;
    const int half   = ntiles >> 1;

    // ---- prefetch first pair's x ----
    float2 pA0, pA1, pA2, pB0, pB1, pB2;
    int tile = blockIdx.x;
    if (tile < half) {
        const float* xa = x + (size_t)(tile * TILE + wid * 32 + lane) * 6;
        pA0 = *reinterpret_cast<const float2*>(xa);
        pA1 = *reinterpret_cast<const float2*>(xa + 2);
        pA2 = *reinterpret_cast<const float2*>(xa + 4);
        const float* xb = x + (size_t)((tile + half) * TILE + wid * 32 + lane) * 6;
        pB0 = *reinterpret_cast<const float2*>(xb);
        pB1 = *reinterpret_cast<const float2*>(xb + 2);
        pB2 = *reinterpret_cast<const float2*>(xb + 4);
    }

    #pragma unroll 1
    for (; tile < half; tile += gridDim.x) {
        const int rowA = tile * TILE + wid * 32;
        const int rowB = (tile + half) * TILE + wid * 32;

        // ---- stage fp32 pts into xb; pack views for C0's MMA path ----
        xbA[lane*4+0] = pA0.x; xbA[lane*4+1] = pA0.y; xbA[lane*4+2] = pA1.x;
        xbB[lane*4+0] = pB0.x; xbB[lane*4+1] = pB0.y; xbB[lane*4+2] = pB1.x;
        const uint32_t wA8 = pack2(pA1.y, pA2.x), wA9 = pack2(pA2.y, 0.0f);
        const uint32_t wB8 = pack2(pB1.y, pB2.x), wB9 = pack2(pB2.y, 0.0f);
        __syncwarp();

        const int tnext = tile + gridDim.x;
        if (tnext < half) {
            const float* xa = x + (size_t)(tnext * TILE + wid * 32 + lane) * 6;
            pA0 = *reinterpret_cast<const float2*>(xa);
            pA1 = *reinterpret_cast<const float2*>(xa + 2);
            pA2 = *reinterpret_cast<const float2*>(xa + 4);
            const float* xb = x + (size_t)((tnext + half) * TILE + wid * 32 + lane) * 6;
            pB0 = *reinterpret_cast<const float2*>(xb);
            pB1 = *reinterpret_cast<const float2*>(xb + 2);
            pB2 = *reinterpret_cast<const float2*>(xb + 4);
        }

        uint32_t A0a[2][4][4], A1a[2][4][4], A0b[2][4][4], A1b[2][4][4];

        // ======== S0: 3 -> 64 SCALAR fp32 (exact), results -> A1 frags ========
        {
            float xA[2][2][3], xB[2][2][3];
            #pragma unroll
            for (int b = 0; b < 2; b++)
                #pragma unroll
                for (int rsel = 0; rsel < 2; rsel++) {
                    int r = b*16 + g4 + rsel*8;
                    xA[b][rsel][0] = xbA[r*4+0]; xA[b][rsel][1] = xbA[r*4+1]; xA[b][rsel][2] = xbA[r*4+2];
                    xB[b][rsel][0] = xbB[r*4+0]; xB[b][rsel][1] = xbB[r*4+1]; xB[b][rsel][2] = xbB[r*4+2];
                }
            #pragma unroll
            for (int np = 0; np < 4; np++) {
                const int ci = 8*np + m4;        // float2 index of col pair (16np+2m4)
                float2 w0p = ws0f2[ci],     w1p = ws0f2[32 + ci], w2p = ws0f2[64 + ci];
                float2 w0q = ws0f2[ci + 4], w1q = ws0f2[36 + ci], w2q = ws0f2[68 + ci];
                #pragma unroll
                for (int b = 0; b < 2; b++)
                    #pragma unroll
                    for (int rsel = 0; rsel < 2; rsel++) {
                        const float* xa = xA[b][rsel];
                        float h0 = fmaf(xa[0], w0p.x, fmaf(xa[1], w1p.x, xa[2] * w2p.x));
                        float h1 = fmaf(xa[0], w0p.y, fmaf(xa[1], w1p.y, xa[2] * w2p.y));
                        float h2 = fmaf(xa[0], w0q.x, fmaf(xa[1], w1q.x, xa[2] * w2q.x));
                        float h3 = fmaf(xa[0], w0q.y, fmaf(xa[1], w1q.y, xa[2] * w2q.y));
                        A1a[b][np][rsel]     = relu2(pack2(h0, h1));
                        A1a[b][np][2 + rsel] = relu2(pack2(h2, h3));
                        const float* xv = xB[b][rsel];
                        float g0 = fmaf(xv[0], w0p.x, fmaf(xv[1], w1p.x, xv[2] * w2p.x));
                        float g1 = fmaf(xv[0], w0p.y, fmaf(xv[1], w1p.y, xv[2] * w2p.y));
                        float g2 = fmaf(xv[0], w0q.x, fmaf(xv[1], w1q.x, xv[2] * w2q.x));
                        float g3 = fmaf(xv[0], w0q.y, fmaf(xv[1], w1q.y, xv[2] * w2q.y));
                        A1b[b][np][rsel]     = relu2(pack2(g0, g1));
                        A1b[b][np][2 + rsel] = relu2(pack2(g2, g3));
                    }
            }
        }

        // ---- S1: 64 -> 64 (dual-tile fused) ----
        layer_h2<4, ST_64, RB_S1>(a144, A1a, A1b, A0a, A0b);

        // ---- S2: 64 -> 16 (fp32 acc, no relu), dual-tile fused ----
        float CsA[2][2][4], CsB[2][2][4];
        {
            #pragma unroll
            for (int b = 0; b < 2; b++)
                #pragma unroll
                for (int j = 0; j < 2; j++)
                    #pragma unroll
                    for (int i = 0; i < 4; i++) { CsA[b][j][i] = 0.0f; CsB[b][j][i] = 0.0f; }
            uint32_t bh[2][4];
            ldm4(bh[0], a144 + (uint32_t)RB_S2);
            #pragma unroll
            for (int kt = 0; kt < 4; kt++) {
                if (kt + 1 < 4)
                    ldm4(bh[(kt + 1) & 1], a144 + (uint32_t)(RB_S2 + (kt + 1) * 32));
                const uint32_t* cur = bh[kt & 1];
                #pragma unroll
                for (int b = 0; b < 2; b++) {
                    mma16816(CsA[b][0], A0a[b][kt], cur[0], cur[1]);
                    mma16816(CsA[b][1], A0a[b][kt], cur[2], cur[3]);
                    mma16816(CsB[b][0], A0b[b][kt], cur[0], cur[1]);
                    mma16816(CsB[b][1], A0b[b][kt], cur[2], cur[3]);
                }
            }
        }

        // sigma (lane m4==0 holds col 0 for rows r0/r1), both tiles
        #pragma unroll
        for (int b = 0; b < 2; b++) {
            if (m4 == 0) {
                int r0 = b*16 + g4, r1 = r0 + 8;
                float a0 = CsA[b][0][0], a2v = CsA[b][0][2];
                outbA[r0*5 + 3] = fmaxf(a0, 0.f) + log1pf(expf(-fabsf(a0)));
                outbA[r1*5 + 3] = fmaxf(a2v, 0.f) + log1pf(expf(-fabsf(a2v)));
                float b0v = CsB[b][0][0], b2v = CsB[b][0][2];
                outbB[r0*5 + 3] = fmaxf(b0v, 0.f) + log1pf(expf(-fabsf(b0v)));
                outbB[r1*5 + 3] = fmaxf(b2v, 0.f) + log1pf(expf(-fabsf(b2v)));
            }
        }

        // ---- build C0 A frags: kt=0 in-lane repack of S2 C-frags; kt=1 views via shfl ----
        #pragma unroll
        for (int b = 0; b < 2; b++) {
            int r0 = b*16 + g4, r1 = r0 + 8;
            A0a[b][0][0] = pack2(CsA[b][0][0], CsA[b][0][1]);
            A0a[b][0][1] = pack2(CsA[b][0][2], CsA[b][0][3]);
            A0a[b][0][2] = pack2(CsA[b][1][0], CsA[b][1][1]);
            A0a[b][0][3] = pack2(CsA[b][1][2], CsA[b][1][3]);
            uint32_t vA00 = shfl_u(wA8, r0), vA01 = shfl_u(wA9, r0);
            uint32_t vA10 = shfl_u(wA8, r1), vA11 = shfl_u(wA9, r1);
            A0a[b][1][0] = (m4 == 0) ? vA00 : (m4 == 1) ? vA01 : 0u;
            A0a[b][1][1] = (m4 == 0) ? vA10 : (m4 == 1) ? vA11 : 0u;
            A0a[b][1][2] = 0u; A0a[b][1][3] = 0u;

            A0b[b][0][0] = pack2(CsB[b][0][0], CsB[b][0][1]);
            A0b[b][0][1] = pack2(CsB[b][0][2], CsB[b][0][3]);
            A0b[b][0][2] = pack2(CsB[b][1][0], CsB[b][1][1]);
            A0b[b][0][3] = pack2(CsB[b][1][2], CsB[b][1][3]);
            uint32_t vB00 = shfl_u(wB8, r0), vB01 = shfl_u(wB9, r0);
            uint32_t vB10 = shfl_u(wB8, r1), vB11 = shfl_u(wB9, r1);
            A0b[b][1][0] = (m4 == 0) ? vB00 : (m4 == 1) ? vB01 : 0u;
            A0b[b][1][1] = (m4 == 0) ? vB10 : (m4 == 1) ? vB11 : 0u;
            A0b[b][1][2] = 0u; A0b[b][1][3] = 0u;
        }

        // ---- C0: 32 -> 64; C1, C2: 64 -> 64 (dual-tile fused) ----
        layer_h2<2, ST_C0, RB_C0>(a80,  A0a, A0b, A1a, A1b);
        layer_h2<4, ST_64, RB_C1>(a144, A1a, A1b, A0a, A0b);
        layer_h2<4, ST_64, RB_C2>(a144, A0a, A0b, A1a, A1b);

        // ---- C3: 64 -> 3 (fp32 acc, N padded to 8) ----
        {
            float CcA[2][4], CcB[2][4];
            #pragma unroll
            for (int b = 0; b < 2; b++)
                #pragma unroll
                for (int i = 0; i < 4; i++) { CcA[b][i] = 0.0f; CcB[b][i] = 0.0f; }
            uint32_t bh[2][2];
            ldm2(bh[0], a2 + (uint32_t)RB_C3);
            #pragma unroll
            for (int kt = 0; kt < 4; kt++) {
                if (kt + 1 < 4)
                    ldm2(bh[(kt + 1) & 1], a2 + (uint32_t)(RB_C3 + (kt + 1) * 32));
                const uint32_t* cur = bh[kt & 1];
                #pragma unroll
                for (int b = 0; b < 2; b++) {
                    mma16816(CcA[b], A1a[b][kt], cur[0], cur[1]);
                    mma16816(CcB[b], A1b[b][kt], cur[0], cur[1]);
                }
            }
            #pragma unroll
            for (int b = 0; b < 2; b++) {
                int r0 = b*16 + g4, r1 = r0 + 8;
                if (m4 == 0) {
                    outbA[r0*5+0] = CcA[b][0]; outbA[r0*5+1] = CcA[b][1];
                    outbA[r1*5+0] = CcA[b][2]; outbA[r1*5+1] = CcA[b][3];
                    outbB[r0*5+0] = CcB[b][0]; outbB[r0*5+1] = CcB[b][1];
                    outbB[r1*5+0] = CcB[b][2]; outbB[r1*5+1] = CcB[b][3];
                } else if (m4 == 1) {
                    outbA[r0*5+2] = CcA[b][0];
                    outbA[r1*5+2] = CcA[b][2];
                    outbB[r0*5+2] = CcB[b][0];
                    outbB[r1*5+2] = CcB[b][2];
                }
            }
        }
        __syncwarp();

        // ---- final stores: lane l writes row l of each tile ----
        {
            float4 rA;
            rA.x = outbA[lane*5+0]; rA.y = outbA[lane*5+1];
            rA.z = outbA[lane*5+2]; rA.w = outbA[lane*5+3];
            reinterpret_cast<float4*>(out)[rowA + lane] = rA;
            float4 rB;
            rB.x = outbB[lane*5+0]; rB.y = outbB[lane*5+1];
            rB.z = outbB[lane*5+2]; rB.w = outbB[lane*5+3];
            reinterpret_cast<float4*>(out)[rowB + lane] = rB;
        }
        __syncwarp();
    }
}

extern "C" void kernel_launch(void* const* d_in, const int* in_sizes, int n_in,
                              void* d_out, int out_size) {
    const float* x   = (const float*)d_in[0];
    const float* ws0 = (const float*)d_in[1];
    const float* ws1 = (const float*)d_in[2];
    const float* ws2 = (const float*)d_in[3];
    const float* wc0 = (const float*)d_in[4];
    const float* wc1 = (const float*)d_in[5];
    const float* wc2 = (const float*)d_in[6];
    const float* wc3 = (const float*)d_in[7];
    float* out = (float*)d_out;

    int n = in_sizes[0] / 6;
    int ntiles = n / TILE;
    int half = ntiles >> 1;

    cudaFuncSetAttribute(nerf_hmma_kernel,
                         cudaFuncAttributeMaxDynamicSharedMemorySize, SMEM_TOTAL);
    int grid = 296;                      // 2 persistent CTAs per SM
    if (grid > half) grid = half;
    nerf_hmma_kernel<<<grid, TPB, SMEM_TOTAL>>>(x, ws0, ws1, ws2, wc0, wc1, wc2, wc3, out, n);
}